// round 6
// baseline (speedup 1.0000x reference)
#include <cuda_runtime.h>
#include <cuda_fp16.h>
#include <cstdint>

#define T_LEN   4096
#define D_DIM   256
#define ATT     50
#define NPAD    64
#define CH      64      // rows per chunk
#define XS      264     // x row stride (floats): 264 % 32 == 8 -> conflict-free LDS.64 A loads & phase-3 reads
#define WS2     72      // W half2 row stride: 72 % 32 == 8 -> conflict-free B staging reads
#define NBATCH  64
#define NCHUNK  (NBATCH * (T_LEN / CH))   // 4096
#define GRID    152
#define EPS     1e-7f

__device__ float    g_acc[NBATCH * D_DIM];   // zero-init at load; reset by last CTA
__device__ float    g_denom[NBATCH];
__device__ unsigned g_done;

__device__ __forceinline__ float tanh_fast(float v) {
    float r;
    asm("tanh.approx.f32 %0, %1;" : "=f"(r) : "f"(v));
    return r;
}
__device__ __forceinline__ uint32_t h2u(__half2 h) {
    return *reinterpret_cast<uint32_t*>(&h);
}

__global__ __launch_bounds__(256, 1)
void att_kernel(const float* __restrict__ x,
                const float* __restrict__ Wg,
                const float* __restrict__ bg,
                const float* __restrict__ ug,
                float* __restrict__ out) {
    extern __shared__ float sm[];
    float*   xs  = sm;                              // 2 * CH * XS floats
    __half2* Wh  = (__half2*)(sm + 2 * CH * XS);    // 128 * WS2 half2
    float*   us  = (float*)(Wh + 128 * WS2);        // NPAD
    float*   bs  = us + NPAD;                       // NPAD
    float*   es  = bs + NPAD;                       // CH
    float*   p0  = es + CH;                         // CH
    float*   p1  = p0 + CH;                         // CH

    const int tid  = threadIdx.x;
    const int lane = tid & 31;
    const int warp = tid >> 5;
    const int g = lane >> 2;
    const int t = lane & 3;
    const int mrow  = (warp & 3) * 16;
    const int cbase = (warp >> 2) * 32;

    auto prefetch = [&](int c, int bufidx) {
        const float* xg = x + ((size_t)(c >> 6) * T_LEN + (size_t)(c & 63) * CH) * D_DIM;
        float* dst = xs + bufidx * (CH * XS);
        #pragma unroll
        for (int j = 0; j < 16; j++) {
            int i  = j * 256 + tid;
            int r  = i >> 6;
            int c4 = i & 63;
            uint32_t sa = (uint32_t)__cvta_generic_to_shared(dst + r * XS + c4 * 4);
            const float4* src = (const float4*)xg + (size_t)r * 64 + c4;
            asm volatile("cp.async.cg.shared.global [%0], [%1], 16;" :: "r"(sa), "l"(src));
        }
        asm volatile("cp.async.commit_group;");
    };

    // ---- Kick off chunk-0 load immediately (overlaps W staging) ----
    const int c0 = blockIdx.x;
    prefetch(c0, 0);

    // ---- Stage W as fp16 half2-along-k into SMEM (per CTA, from L2) ----
    for (int i = tid; i < 128 * 64; i += 256) {
        int k2 = i >> 6, n = i & 63;
        float w0 = (n < ATT) ? Wg[(2 * k2)     * ATT + n] : 0.0f;
        float w1 = (n < ATT) ? Wg[(2 * k2 + 1) * ATT + n] : 0.0f;
        Wh[k2 * WS2 + n] = __floats2half2_rn(w0, w1);
    }
    if (tid < NPAD) {
        us[tid] = (tid < ATT) ? ug[tid] : 0.0f;
        bs[tid] = (tid < ATT) ? bg[tid] : 0.0f;
    }
    __syncthreads();

    // ---- Hoist this warp's B fragments into registers (loop-invariant) ----
    uint32_t B0[16][4], B1[16][4];
    #pragma unroll
    for (int ks = 0; ks < 16; ks++) {
        const __half2* wk0 = Wh + (8 * ks + t) * WS2 + cbase;
        const __half2* wk1 = wk0 + 4 * WS2;
        #pragma unroll
        for (int nt = 0; nt < 4; nt++) {
            B0[ks][nt] = h2u(wk0[nt * 8 + g]);
            B1[ks][nt] = h2u(wk1[nt * 8 + g]);
        }
    }

    // ---- Main persistent loop ----
    int it = 0;
    for (int c = c0; c < NCHUNK; c += GRID, it++) {
        const int nb = it & 1;
        const int cn = c + GRID;
        if (cn < NCHUNK) {
            prefetch(cn, nb ^ 1);
            asm volatile("cp.async.wait_group 1;" ::: "memory");
        } else {
            asm volatile("cp.async.wait_group 0;" ::: "memory");
        }
        __syncthreads();

        const float* cur = xs + nb * (CH * XS);
        const int b = c >> 6;

        // ---- Phase 2: fp16 MMA, B from registers ----
        float acc[4][4];
        #pragma unroll
        for (int nt = 0; nt < 4; nt++) {
            acc[nt][0] = 0.f; acc[nt][1] = 0.f; acc[nt][2] = 0.f; acc[nt][3] = 0.f;
        }
        const float* xr0 = cur + (mrow + g) * XS;
        const float* xr1 = xr0 + 8 * XS;

        #pragma unroll
        for (int ks = 0; ks < 16; ks++) {
            const int k0 = ks * 16;
            float2 f0 = *(const float2*)&xr0[k0 + 2 * t];
            float2 f1 = *(const float2*)&xr1[k0 + 2 * t];
            float2 f2 = *(const float2*)&xr0[k0 + 2 * t + 8];
            float2 f3 = *(const float2*)&xr1[k0 + 2 * t + 8];
            uint32_t a0 = h2u(__floats2half2_rn(f0.x, f0.y));
            uint32_t a1 = h2u(__floats2half2_rn(f1.x, f1.y));
            uint32_t a2 = h2u(__floats2half2_rn(f2.x, f2.y));
            uint32_t a3 = h2u(__floats2half2_rn(f3.x, f3.y));
            #pragma unroll
            for (int nt = 0; nt < 4; nt++) {
                asm volatile(
                    "mma.sync.aligned.m16n8k16.row.col.f32.f16.f16.f32 "
                    "{%0,%1,%2,%3}, {%4,%5,%6,%7}, {%8,%9}, {%0,%1,%2,%3};"
                    : "+f"(acc[nt][0]), "+f"(acc[nt][1]),
                      "+f"(acc[nt][2]), "+f"(acc[nt][3])
                    : "r"(a0), "r"(a1), "r"(a2), "r"(a3),
                      "r"(B0[ks][nt]), "r"(B1[ks][nt]));
            }
        }

        float slo = 0.f, shi = 0.f;
        #pragma unroll
        for (int nt = 0; nt < 4; nt++) {
            int col = cbase + nt * 8 + 2 * t;
            float u0 = us[col], u1 = us[col + 1];
            float Bb0 = bs[col], Bb1 = bs[col + 1];
            slo += tanh_fast(acc[nt][0] + Bb0) * u0 + tanh_fast(acc[nt][1] + Bb1) * u1;
            shi += tanh_fast(acc[nt][2] + Bb0) * u0 + tanh_fast(acc[nt][3] + Bb1) * u1;
        }
        slo += __shfl_xor_sync(0xFFFFFFFFu, slo, 1);
        slo += __shfl_xor_sync(0xFFFFFFFFu, slo, 2);
        shi += __shfl_xor_sync(0xFFFFFFFFu, shi, 1);
        shi += __shfl_xor_sync(0xFFFFFFFFu, shi, 2);
        if (t == 0) {
            float* pp = (warp >= 4) ? p1 : p0;
            pp[mrow + g]     = slo;
            pp[mrow + g + 8] = shi;
        }
        __syncthreads();

        // ---- exp + denominator (warp 0) ----
        if (warp == 0) {
            float e0 = __expf(p0[lane]      + p1[lane]);
            float e1 = __expf(p0[lane + 32] + p1[lane + 32]);
            es[lane]      = e0;
            es[lane + 32] = e1;
            float s = e0 + e1;
            #pragma unroll
            for (int o = 16; o > 0; o >>= 1) s += __shfl_xor_sync(0xFFFFFFFFu, s, o);
            if (lane == 0) atomicAdd(&g_denom[b], s);
        }
        __syncthreads();

        // ---- Phase 3: weighted sum over 64 rows, exact fp32 x ----
        float q0 = 0.f, q1 = 0.f, q2 = 0.f, q3 = 0.f;
        #pragma unroll 16
        for (int r = 0; r < CH; r += 4) {
            q0 += es[r + 0] * cur[(r + 0) * XS + tid];
            q1 += es[r + 1] * cur[(r + 1) * XS + tid];
            q2 += es[r + 2] * cur[(r + 2) * XS + tid];
            q3 += es[r + 3] * cur[(r + 3) * XS + tid];
        }
        atomicAdd(&g_acc[b * D_DIM + tid], (q0 + q1) + (q2 + q3));

        __syncthreads();  // buffer + es/p reuse before next prefetch
    }

    // ---- Last CTA normalizes into d_out and resets scratch ----
    __shared__ unsigned is_last;
    __syncthreads();
    if (tid == 0) {
        __threadfence();
        unsigned old = atomicAdd(&g_done, 1u);
        is_last = (old == GRID - 1) ? 1u : 0u;
    }
    __syncthreads();
    if (is_last) {
        __threadfence();
        for (int i = tid; i < NBATCH * D_DIM; i += 256) {
            out[i] = g_acc[i] / (g_denom[i >> 8] + EPS);
            g_acc[i] = 0.0f;
        }
        __syncthreads();
        if (tid < NBATCH) g_denom[tid] = 0.0f;
        __threadfence();
        if (tid == 0) atomicExch(&g_done, 0u);
    }
}

extern "C" void kernel_launch(void* const* d_in, const int* in_sizes, int n_in,
                              void* d_out, int out_size) {
    const float* x = (const float*)d_in[0];
    const float* W = (const float*)d_in[1];
    const float* b = (const float*)d_in[2];
    const float* u = (const float*)d_in[3];
    float* out = (float*)d_out;

    const int smem_bytes = (2 * CH * XS) * 4 + (128 * WS2) * 4 + (2 * NPAD + 3 * CH) * 4;
    cudaFuncSetAttribute(att_kernel,
                         cudaFuncAttributeMaxDynamicSharedMemorySize, smem_bytes);

    att_kernel<<<GRID, 256, smem_bytes>>>(x, W, b, u, out);
}